// round 10
// baseline (speedup 1.0000x reference)
#include <cuda_runtime.h>
#include <cuda_fp16.h>

// ---------------------------------------------------------------------------
// WavePlaneField: 6 planes reconstructed via 2-level inverse DWT (coif4,
// periodization), bilinear-sampled at N points, channelwise product.
//
// Phase 1 (4 kernels): separable inverse DWT per plane -> g_planes2, an
//   x-paired fp16 layout: element (y,x,c) = half2(v[y,x,c], v[y,x+1,c]).
//   Stage1/3 are float4-vectorized along x; stage2/4 use paired parity.
// Phase 2: warp-per-point sampler (inline coords, 12 half2 loads/point).
// ---------------------------------------------------------------------------

#define CCH 32

// All planes have H=256. W per plane:
__constant__ int c_W[6]    = {256, 256, 64, 256, 64, 64};
__constant__ int c_POFF[6] = {0, 65536, 131072, 147456, 212992, 229376}; // pixel offsets

// coif4 reconstruction filters (24 taps)
__constant__ float REC_LO_C[24] = {
    0.0008923136685823146f, -0.0016294920126017326f, -0.0073461663276420935f,
    0.016068943964776348f, 0.026682300156053072f, -0.08126669968087875f,
    -0.05607731331675481f, 0.41530840703043026f, 0.782238930920499f,
    0.4343860564914685f, -0.06662747426342504f, -0.09622044203398798f,
    0.03933442712333749f, 0.025082261844864097f, -0.015211731527946259f,
    -0.00565828668661072f, 0.003751436157278457f, 0.0012665619292989445f,
    -0.0005890207562443383f, -0.00025997455248771324f, 6.233903446100713e-05f,
    3.1229875865345646e-05f, -3.2596802368833675e-06f, -1.7849850030882614e-06f
};
__constant__ float REC_HI_C[24] = {
    -1.7849850030882614e-06f, 3.2596802368833675e-06f, 3.1229875865345646e-05f,
    -6.233903446100713e-05f, -0.00025997455248771324f, 0.0005890207562443383f,
    0.0012665619292989445f, -0.003751436157278457f, -0.00565828668661072f,
    0.015211731527946259f, 0.025082261844864097f, -0.03933442712333749f,
    -0.09622044203398798f, 0.06662747426342504f, 0.4343860564914685f,
    -0.782238930920499f, 0.41530840703043026f, 0.05607731331675481f,
    -0.08126669968087875f, -0.026682300156053072f, 0.016068943964776348f,
    0.0073461663276420935f, -0.0016294920126017326f, -0.0008923136685823146f
};

// Scratch (static device globals; per-plane strides sized for the largest plane)
#define S_LO1 262144    // C*128*64
#define S_MID 524288    // C*128*128
#define S_LO2 1048576   // C*256*128
__device__ float g_lo1[6 * S_LO1];
__device__ float g_hi1[6 * S_LO1];
__device__ float g_mid[6 * S_MID];
__device__ float g_lo2[6 * S_LO2];
__device__ float g_hi2[6 * S_LO2];
// x-paired fp16 planes: [pixel][c] = half2(v[y,x,c], v[y,min(x+1,W-1),c])
__device__ __half2 g_planes2[245760 * CCH];

struct CoefPtrs {
    const float* yl[6];
    const float* yha[6];
    const float* yhb[6];
};

__device__ __forceinline__ float4 f4fma(float a, float4 x, float4 acc) {
    acc.x += a * x.x; acc.y += a * x.y; acc.z += a * x.z; acc.w += a * x.w;
    return acc;
}

// Stage 1 (float4 over x): level-1 H-axis synthesis.
// in: yl[C,64,w4], yhb[C,3,64,w4] -> lo1,hi1 [C,128,w4]
__global__ void k_stage1(CoefPtrs P) {
    const int pl = blockIdx.y;
    const int w4 = c_W[pl] >> 2;
    const int w4v = w4 >> 2;                 // float4 columns
    const int n = CCH * 128 * w4v;
    const int tid = blockIdx.x * blockDim.x + threadIdx.x;
    if (tid >= n) return;
    const int xv = tid % w4v;
    const int i = (tid / w4v) & 127;
    const int c = tid / (w4v * 128);
    const int s = i >> 1, p = i & 1;
    const float* yl = P.yl[pl];
    const float* yhb = P.yhb[pl];
    const int bandStride = 64 * w4;          // floats
    float4 lo = make_float4(0, 0, 0, 0), hi = make_float4(0, 0, 0, 0);
#pragma unroll
    for (int m = 0; m < 12; m++) {
        int row = s - m; if (row < 0) row += 64;
        const float fl = REC_LO_C[2 * m + p];
        const float fh = REC_HI_C[2 * m + p];
        const float4 a  = ((const float4*)(yl  + (c * 64 + row) * w4))[xv];
        const float4 b0 = ((const float4*)(yhb + ((c * 3 + 0) * 64 + row) * w4))[xv];
        const float4 b1 = ((const float4*)(yhb + ((c * 3 + 0) * 64 + row) * w4 + bandStride))[xv];
        const float4 b2 = ((const float4*)(yhb + ((c * 3 + 0) * 64 + row) * w4 + 2 * bandStride))[xv];
        lo = f4fma(fl, a,  lo); lo = f4fma(fh, b0, lo);
        hi = f4fma(fl, b1, hi); hi = f4fma(fh, b2, hi);
    }
    ((float4*)(g_lo1 + pl * S_LO1 + (c * 128 + i) * w4))[xv] = lo;
    ((float4*)(g_hi1 + pl * S_LO1 + (c * 128 + i) * w4))[xv] = hi;
}

// Stage 2 (paired parity): level-1 W-axis synthesis.
// in: lo1,hi1 [C,128,w4] -> mid [C,128,w2]. One thread -> outputs j=2s,2s+1.
__global__ void k_stage2() {
    const int pl = blockIdx.y;
    const int w2 = c_W[pl] >> 1;
    const int w4 = w2 >> 1;
    const int n = CCH * 128 * w4;            // pairs
    const int tid = blockIdx.x * blockDim.x + threadIdx.x;
    if (tid >= n) return;
    const int s = tid % w4;
    const int i = (tid / w4) & 127;
    const int c = tid / (w4 * 128);
    const int base = pl * S_LO1 + (c * 128 + i) * w4;
    float v0 = 0.f, v1 = 0.f;
#pragma unroll
    for (int m = 0; m < 12; m++) {
        int col = s - m; if (col < 0) col += w4;
        const float lv = g_lo1[base + col];
        const float hv = g_hi1[base + col];
        v0 += REC_LO_C[2 * m]     * lv + REC_HI_C[2 * m]     * hv;
        v1 += REC_LO_C[2 * m + 1] * lv + REC_HI_C[2 * m + 1] * hv;
    }
    const int ob = pl * S_MID + (c * 128 + i) * w2 + 2 * s;
    g_mid[ob]     = v0;
    g_mid[ob + 1] = v1;
}

// Stage 3 (float4 over x): level-2 H-axis synthesis.
// in: mid [C,128,w2], yha [C,3,128,w2] -> lo2,hi2 [C,256,w2]
__global__ void k_stage3(CoefPtrs P) {
    const int pl = blockIdx.y;
    const int w2 = c_W[pl] >> 1;
    const int w2v = w2 >> 2;
    const int n = CCH * 256 * w2v;
    const int tid = blockIdx.x * blockDim.x + threadIdx.x;
    if (tid >= n) return;
    const int xv = tid % w2v;
    const int i = (tid / w2v) & 255;
    const int c = tid / (w2v * 256);
    const int s = i >> 1, p = i & 1;
    const float* yha = P.yha[pl];
    const int bandStride = 128 * w2;
    const float* midP = g_mid + pl * S_MID;
    float4 lo = make_float4(0, 0, 0, 0), hi = make_float4(0, 0, 0, 0);
#pragma unroll
    for (int m = 0; m < 12; m++) {
        int row = s - m; if (row < 0) row += 128;
        const float fl = REC_LO_C[2 * m + p];
        const float fh = REC_HI_C[2 * m + p];
        const float4 a  = ((const float4*)(midP + (c * 128 + row) * w2))[xv];
        const float4 b0 = ((const float4*)(yha + ((c * 3 + 0) * 128 + row) * w2))[xv];
        const float4 b1 = ((const float4*)(yha + ((c * 3 + 0) * 128 + row) * w2 + bandStride))[xv];
        const float4 b2 = ((const float4*)(yha + ((c * 3 + 0) * 128 + row) * w2 + 2 * bandStride))[xv];
        lo = f4fma(fl, a,  lo); lo = f4fma(fh, b0, lo);
        hi = f4fma(fl, b1, hi); hi = f4fma(fh, b2, hi);
    }
    ((float4*)(g_lo2 + pl * S_LO2 + (c * 256 + i) * w2))[xv] = lo;
    ((float4*)(g_hi2 + pl * S_LO2 + (c * 256 + i) * w2))[xv] = hi;
}

// Stage 4 (row-tiled, paired-parity, x-paired output): level-2 W-axis
// synthesis + transpose to x-paired half2 layout. One block per (plane, y).
__global__ void __launch_bounds__(256) k_stage4() {
    const int pl = blockIdx.y;
    const int W = c_W[pl];
    const int w2 = W >> 1;
    const int y = blockIdx.x;

    __shared__ float lo_s[32][129];
    __shared__ float hi_s[32][129];
    __shared__ float out_s[256][33];   // [x][c]

    const int sh = (w2 == 128) ? 7 : 5;          // log2(w2)
    const int rowBase = pl * S_LO2 + y * w2;     // + c*256*w2 per channel
    for (int t = threadIdx.x; t < 32 * w2; t += 256) {
        const int c = t >> sh;
        const int col = t & (w2 - 1);
        const int gi = rowBase + c * (256 * w2) + col;
        lo_s[c][col] = g_lo2[gi];
        hi_s[c][col] = g_hi2[gi];
    }
    __syncthreads();

    const int nPairs = w2 * CCH;                  // one thread -> 2 outputs
    for (int t = threadIdx.x; t < nPairs; t += 256) {
        const int c = t & 31;
        const int s = t >> 5;
        float v0 = 0.f, v1 = 0.f;                 // parity 0 / parity 1
#pragma unroll
        for (int m = 0; m < 12; m++) {
            int col = s - m; if (col < 0) col += w2;
            const float lv = lo_s[c][col];
            const float hv = hi_s[c][col];
            v0 += REC_LO_C[2 * m]     * lv + REC_HI_C[2 * m]     * hv;
            v1 += REC_LO_C[2 * m + 1] * lv + REC_HI_C[2 * m + 1] * hv;
        }
        out_s[2 * s][c]     = v0;
        out_s[2 * s + 1][c] = v1;
    }
    __syncthreads();

    __half2* __restrict__ outRow = g_planes2 + ((size_t)(c_POFF[pl] + y * W)) * CCH;
    const int n = W * CCH;
    for (int t = threadIdx.x; t < n; t += 256) {
        const int c = t & 31;
        const int x = t >> 5;
        const int x1 = (x + 1 < W) ? x + 1 : W - 1;
        outRow[x * CCH + c] = __floats2half2_rn(out_s[x][c], out_s[x1][c]);
    }
}

// Phase 2: warp per point, lane = channel. Inline coord math (lane-redundant
// but proven cheap), 12 half2 plane loads per point (x-corners paired).
__global__ void __launch_bounds__(256) k_sample(const float* __restrict__ pts,
                                                const float* __restrict__ ts,
                                                float* __restrict__ out,
                                                int nPts) {
    const int warp = (blockIdx.x * blockDim.x + threadIdx.x) >> 5;
    const int lane = threadIdx.x & 31;
    if (warp >= nPts) return;

    const float inv = -1.0f / 1.3f;   // pts_n = -pts/B
    float p4[4];
    p4[0] = pts[warp * 3 + 0] * inv;
    p4[1] = pts[warp * 3 + 1] * inv;
    p4[2] = pts[warp * 3 + 2] * inv;
    p4[3] = ts[warp] * 2.0f - 1.0f;

    constexpr int QIDX[6] = {0, 0, 3, 1, 3, 3};
    constexpr int RIDX[6] = {1, 2, 0, 2, 1, 2};
    constexpr int PW[6]   = {256, 256, 64, 256, 64, 64};
    constexpr int POFF[6] = {0, 65536, 131072, 147456, 212992, 229376};

    float prod = 1.0f;
#pragma unroll
    for (int ii = 0; ii < 6; ii++) {
        const int W = PW[ii];
        const float cx = p4[QIDX[ii]];
        const float cy = p4[RIDX[ii]];
        float xf = fminf(fmaxf((cx + 1.0f) * 0.5f * (float)(W - 1), 0.0f), (float)(W - 1));
        float yf = fminf(fmaxf((cy + 1.0f) * 0.5f * 255.0f, 0.0f), 255.0f);
        float x0f = fminf(fmaxf(floorf(xf), 0.0f), (float)(W - 2));
        float y0f = fminf(fmaxf(floorf(yf), 0.0f), 254.0f);
        const float wx = xf - x0f;
        const float wy = yf - y0f;
        const int i00 = (POFF[ii] + (int)y0f * W + (int)x0f) * CCH + lane;
        const __half2 a = g_planes2[i00];                  // (v00, v01)
        const __half2 b = g_planes2[i00 + W * CCH];        // (v10, v11)
        const float2 fa = __half22float2(a);
        const float2 fb = __half22float2(b);
        const float r0 = fa.x + wx * (fa.y - fa.x);
        const float r1 = fb.x + wx * (fb.y - fb.x);
        prod *= r0 + wy * (r1 - r0);
    }
    out[(size_t)warp * CCH + lane] = prod;
}

extern "C" void kernel_launch(void* const* d_in, const int* in_sizes, int n_in,
                              void* d_out, int out_size) {
    const float* pts = (const float*)d_in[0];
    const float* ts  = (const float*)d_in[1];
    CoefPtrs P;
    for (int i = 0; i < 6; i++) {
        P.yl[i]  = (const float*)d_in[2 + 3 * i];
        P.yha[i] = (const float*)d_in[3 + 3 * i];
        P.yhb[i] = (const float*)d_in[4 + 3 * i];
    }
    float* out = (float*)d_out;
    const int nPts = in_sizes[1];   // timestamps count = N

    dim3 blk(256);
    // max sizes across planes (largest plane W=256)
    k_stage1<<<dim3((CCH * 128 * 16 + 255) / 256, 6), blk>>>(P);       // w4v max 16
    k_stage2<<<dim3((CCH * 128 * 64 + 255) / 256, 6), blk>>>();        // pairs max w4=64
    k_stage3<<<dim3((CCH * 256 * 32 + 255) / 256, 6), blk>>>(P);       // w2v max 32
    k_stage4<<<dim3(256, 6), blk>>>();

    const int totalThreads = nPts * 32;
    k_sample<<<(totalThreads + 255) / 256, 256>>>(pts, ts, out, nPts);
}

// round 11
// speedup vs baseline: 1.1918x; 1.1918x over previous
#include <cuda_runtime.h>
#include <cuda_fp16.h>

// ---------------------------------------------------------------------------
// WavePlaneField: 6 planes reconstructed via 2-level inverse DWT (coif4,
// periodization), bilinear-sampled at N points, channelwise product.
//
// Phase 1 (4 kernels, R7-proven scalar forms): separable inverse DWT per
//   plane -> g_planes2, x-paired fp16: (y,x,c) = half2(v[y,x,c], v[y,x+1,c]).
// Phase 2: warp-per-point sampler. Lanes 0-5 compute the 6 planes' coords
//   in parallel (coord math was lane-uniform and 6x-serial before); shfl
//   broadcasts feed 12 half2 loads + fp32 interp + product.
// ---------------------------------------------------------------------------

#define CCH 32

// All planes have H=256. W per plane:
__constant__ int c_W[6]    = {256, 256, 64, 256, 64, 64};
__constant__ int c_POFF[6] = {0, 65536, 131072, 147456, 212992, 229376}; // pixel offsets

// coif4 reconstruction filters (24 taps)
__constant__ float REC_LO_C[24] = {
    0.0008923136685823146f, -0.0016294920126017326f, -0.0073461663276420935f,
    0.016068943964776348f, 0.026682300156053072f, -0.08126669968087875f,
    -0.05607731331675481f, 0.41530840703043026f, 0.782238930920499f,
    0.4343860564914685f, -0.06662747426342504f, -0.09622044203398798f,
    0.03933442712333749f, 0.025082261844864097f, -0.015211731527946259f,
    -0.00565828668661072f, 0.003751436157278457f, 0.0012665619292989445f,
    -0.0005890207562443383f, -0.00025997455248771324f, 6.233903446100713e-05f,
    3.1229875865345646e-05f, -3.2596802368833675e-06f, -1.7849850030882614e-06f
};
__constant__ float REC_HI_C[24] = {
    -1.7849850030882614e-06f, 3.2596802368833675e-06f, 3.1229875865345646e-05f,
    -6.233903446100713e-05f, -0.00025997455248771324f, 0.0005890207562443383f,
    0.0012665619292989445f, -0.003751436157278457f, -0.00565828668661072f,
    0.015211731527946259f, 0.025082261844864097f, -0.03933442712333749f,
    -0.09622044203398798f, 0.06662747426342504f, 0.4343860564914685f,
    -0.782238930920499f, 0.41530840703043026f, 0.05607731331675481f,
    -0.08126669968087875f, -0.026682300156053072f, 0.016068943964776348f,
    0.0073461663276420935f, -0.0016294920126017326f, -0.0008923136685823146f
};

// Scratch (static device globals; per-plane strides sized for the largest plane)
#define S_LO1 262144    // C*128*64
#define S_MID 524288    // C*128*128
#define S_LO2 1048576   // C*256*128
__device__ float g_lo1[6 * S_LO1];
__device__ float g_hi1[6 * S_LO1];
__device__ float g_mid[6 * S_MID];
__device__ float g_lo2[6 * S_LO2];
__device__ float g_hi2[6 * S_LO2];
// x-paired fp16 planes: [pixel][c] = half2(v[y,x,c], v[y,min(x+1,W-1),c])
__device__ __half2 g_planes2[245760 * CCH];

struct CoefPtrs {
    const float* yl[6];
    const float* yha[6];
    const float* yhb[6];
};

// Stage 1: level-1 H-axis synthesis. in: yl[C,64,w4], yhb[C,3,64,w4]
// out: lo1,hi1 [C,128,w4]
__global__ void k_stage1(CoefPtrs P) {
    const int pl = blockIdx.y;
    const int w4 = c_W[pl] >> 2;
    const int n = CCH * 128 * w4;
    const int tid = blockIdx.x * blockDim.x + threadIdx.x;
    if (tid >= n) return;
    const int x = tid % w4;
    const int i = (tid / w4) & 127;
    const int c = tid / (w4 * 128);
    const int s = i >> 1, p = i & 1;
    const float* yl = P.yl[pl];
    const float* yhb = P.yhb[pl];
    const int bandStride = 64 * w4;
    float lo = 0.f, hi = 0.f;
#pragma unroll
    for (int m = 0; m < 12; m++) {
        int row = s - m; if (row < 0) row += 64;
        const float fl = REC_LO_C[2 * m + p];
        const float fh = REC_HI_C[2 * m + p];
        const int bi = (c * 64 + row) * w4 + x;
        const int b0 = ((c * 3 + 0) * 64 + row) * w4 + x;
        lo += fl * yl[bi] + fh * yhb[b0];
        hi += fl * yhb[b0 + bandStride] + fh * yhb[b0 + 2 * bandStride];
    }
    g_lo1[pl * S_LO1 + tid] = lo;
    g_hi1[pl * S_LO1 + tid] = hi;
}

// Stage 2: level-1 W-axis synthesis. in: lo1,hi1 [C,128,w4] -> mid [C,128,w2]
__global__ void k_stage2() {
    const int pl = blockIdx.y;
    const int w2 = c_W[pl] >> 1;
    const int w4 = w2 >> 1;
    const int n = CCH * 128 * w2;
    const int tid = blockIdx.x * blockDim.x + threadIdx.x;
    if (tid >= n) return;
    const int j = tid % w2;
    const int i = (tid / w2) & 127;
    const int c = tid / (w2 * 128);
    const int s = j >> 1, p = j & 1;
    const int base = pl * S_LO1 + (c * 128 + i) * w4;
    float v = 0.f;
#pragma unroll
    for (int m = 0; m < 12; m++) {
        int col = s - m; if (col < 0) col += w4;
        v += REC_LO_C[2 * m + p] * g_lo1[base + col]
           + REC_HI_C[2 * m + p] * g_hi1[base + col];
    }
    g_mid[pl * S_MID + tid] = v;
}

// Stage 3: level-2 H-axis synthesis. in: mid [C,128,w2], yha [C,3,128,w2]
// out: lo2,hi2 [C,256,w2]
__global__ void k_stage3(CoefPtrs P) {
    const int pl = blockIdx.y;
    const int w2 = c_W[pl] >> 1;
    const int n = CCH * 256 * w2;
    const int tid = blockIdx.x * blockDim.x + threadIdx.x;
    if (tid >= n) return;
    const int x = tid % w2;
    const int i = (tid / w2) & 255;
    const int c = tid / (w2 * 256);
    const int s = i >> 1, p = i & 1;
    const float* yha = P.yha[pl];
    const int bandStride = 128 * w2;
    const int midBase = pl * S_MID;
    float lo = 0.f, hi = 0.f;
#pragma unroll
    for (int m = 0; m < 12; m++) {
        int row = s - m; if (row < 0) row += 128;
        const float fl = REC_LO_C[2 * m + p];
        const float fh = REC_HI_C[2 * m + p];
        const int bi = (c * 128 + row) * w2 + x;
        const int b0 = ((c * 3 + 0) * 128 + row) * w2 + x;
        lo += fl * g_mid[midBase + bi] + fh * yha[b0];
        hi += fl * yha[b0 + bandStride] + fh * yha[b0 + 2 * bandStride];
    }
    g_lo2[pl * S_LO2 + tid] = lo;
    g_hi2[pl * S_LO2 + tid] = hi;
}

// Stage 4 (row-tiled, paired-parity, x-paired output): level-2 W-axis
// synthesis + transpose to x-paired half2 layout. One block per (plane, y).
__global__ void __launch_bounds__(256) k_stage4() {
    const int pl = blockIdx.y;
    const int W = c_W[pl];
    const int w2 = W >> 1;
    const int y = blockIdx.x;

    __shared__ float lo_s[32][129];
    __shared__ float hi_s[32][129];
    __shared__ float out_s[256][33];   // [x][c]

    const int sh = (w2 == 128) ? 7 : 5;          // log2(w2)
    const int rowBase = pl * S_LO2 + y * w2;     // + c*256*w2 per channel
    for (int t = threadIdx.x; t < 32 * w2; t += 256) {
        const int c = t >> sh;
        const int col = t & (w2 - 1);
        const int gi = rowBase + c * (256 * w2) + col;
        lo_s[c][col] = g_lo2[gi];
        hi_s[c][col] = g_hi2[gi];
    }
    __syncthreads();

    const int nPairs = w2 * CCH;                  // one thread -> 2 outputs
    for (int t = threadIdx.x; t < nPairs; t += 256) {
        const int c = t & 31;
        const int s = t >> 5;
        float v0 = 0.f, v1 = 0.f;                 // parity 0 / parity 1
#pragma unroll
        for (int m = 0; m < 12; m++) {
            int col = s - m; if (col < 0) col += w2;
            const float lv = lo_s[c][col];
            const float hv = hi_s[c][col];
            v0 += REC_LO_C[2 * m]     * lv + REC_HI_C[2 * m]     * hv;
            v1 += REC_LO_C[2 * m + 1] * lv + REC_HI_C[2 * m + 1] * hv;
        }
        out_s[2 * s][c]     = v0;
        out_s[2 * s + 1][c] = v1;
    }
    __syncthreads();

    __half2* __restrict__ outRow = g_planes2 + ((size_t)(c_POFF[pl] + y * W)) * CCH;
    const int n = W * CCH;
    for (int t = threadIdx.x; t < n; t += 256) {
        const int c = t & 31;
        const int x = t >> 5;
        const int x1 = (x + 1 < W) ? x + 1 : W - 1;
        outRow[x * CCH + c] = __floats2half2_rn(out_s[x][c], out_s[x1][c]);
    }
}

// Phase 2: warp per point, lane = channel. Lanes 0-5 compute the 6 planes'
// coords IN PARALLEL (was 6x serial lane-uniform math); shfl broadcasts the
// (base, wx, wy) triples; then 12 half2 loads + fp32 interp + product.
__global__ void __launch_bounds__(256) k_sample(const float* __restrict__ pts,
                                                const float* __restrict__ ts,
                                                float* __restrict__ out,
                                                int nPts) {
    const int warp = (blockIdx.x * blockDim.x + threadIdx.x) >> 5;
    const int lane = threadIdx.x & 31;
    if (warp >= nPts) return;

    const float inv = -1.0f / 1.3f;   // pts_n = -pts/B
    const float p0 = pts[warp * 3 + 0] * inv;
    const float p1 = pts[warp * 3 + 1] * inv;
    const float p2 = pts[warp * 3 + 2] * inv;
    const float p3 = ts[warp] * 2.0f - 1.0f;

    // Per-lane plane coords (lanes 0-5 meaningful):
    // QIDX = {0,0,3,1,3,3} -> cx; RIDX = {1,2,0,2,1,2} -> cy
    const float cx = (lane < 2) ? p0 : ((lane == 3) ? p1 : p3);
    const float cy = (lane == 0 || lane == 4) ? p1
                   : ((lane == 2) ? p0 : p2);
    // W per plane {256,256,64,256,64,64}
    const bool small = (lane == 2 || lane >= 4);
    const float Wm1 = small ? 63.0f : 255.0f;
    const int   Wi  = small ? 64 : 256;
    const int   poff = c_POFF[(lane < 6) ? lane : 0];

    float xf = fminf(fmaxf((cx + 1.0f) * 0.5f * Wm1, 0.0f), Wm1);
    float yf = fminf(fmaxf((cy + 1.0f) * 0.5f * 255.0f, 0.0f), 255.0f);
    float x0f = fminf(floorf(xf), Wm1 - 1.0f);   // xf >= 0 already
    float y0f = fminf(floorf(yf), 254.0f);
    const float wx = xf - x0f;
    const float wy = yf - y0f;
    const int  base = (poff + (int)y0f * Wi + (int)x0f) * CCH;

    constexpr int PW[6] = {256, 256, 64, 256, 64, 64};

    float prod = 1.0f;
#pragma unroll
    for (int ii = 0; ii < 6; ii++) {
        const int   b  = __shfl_sync(0xffffffffu, base, ii);
        const float wxb = __shfl_sync(0xffffffffu, wx, ii);
        const float wyb = __shfl_sync(0xffffffffu, wy, ii);
        const int i00 = b + lane;
        const __half2 a2 = g_planes2[i00];                   // (v00, v01)
        const __half2 b2 = g_planes2[i00 + PW[ii] * CCH];    // (v10, v11)
        const float2 fa = __half22float2(a2);
        const float2 fb = __half22float2(b2);
        const float r0 = fa.x + wxb * (fa.y - fa.x);
        const float r1 = fb.x + wxb * (fb.y - fb.x);
        prod *= r0 + wyb * (r1 - r0);
    }
    out[(size_t)warp * CCH + lane] = prod;
}

extern "C" void kernel_launch(void* const* d_in, const int* in_sizes, int n_in,
                              void* d_out, int out_size) {
    const float* pts = (const float*)d_in[0];
    const float* ts  = (const float*)d_in[1];
    CoefPtrs P;
    for (int i = 0; i < 6; i++) {
        P.yl[i]  = (const float*)d_in[2 + 3 * i];
        P.yha[i] = (const float*)d_in[3 + 3 * i];
        P.yhb[i] = (const float*)d_in[4 + 3 * i];
    }
    float* out = (float*)d_out;
    const int nPts = in_sizes[1];   // timestamps count = N

    dim3 blk(256);
    k_stage1<<<dim3((CCH * 128 * 64 + 255) / 256, 6), blk>>>(P);
    k_stage2<<<dim3((CCH * 128 * 128 + 255) / 256, 6), blk>>>();
    k_stage3<<<dim3((CCH * 256 * 128 + 255) / 256, 6), blk>>>(P);
    k_stage4<<<dim3(256, 6), blk>>>();

    const int totalThreads = nPts * 32;
    k_sample<<<(totalThreads + 255) / 256, 256>>>(pts, ts, out, nPts);
}

// round 12
// speedup vs baseline: 1.5574x; 1.3068x over previous
#include <cuda_runtime.h>
#include <cuda_fp16.h>

// ---------------------------------------------------------------------------
// WavePlaneField: 6 planes reconstructed via 2-level inverse DWT (coif4,
// periodization), bilinear-sampled at N points, channelwise product.
//
// Phase 1: separable inverse DWT per plane -> g_planes2, x-paired fp16:
//   (y,x,c) = half2(v[y,x,c], v[y,x+1,c]).
//   Stage1/2/3 paired-parity (both output parities share all loads);
//   Stage4 row-tiled smem with wrap-padding (immediate-offset taps).
// Phase 2: warp-per-point sampler; lanes 0-5 compute the 6 planes' coords
//   in parallel, shfl broadcast, 12 half2 loads + fp32 interp + product.
// ---------------------------------------------------------------------------

#define CCH 32

// All planes have H=256. W per plane:
__constant__ int c_W[6]    = {256, 256, 64, 256, 64, 64};
__constant__ int c_POFF[6] = {0, 65536, 131072, 147456, 212992, 229376}; // pixel offsets

// coif4 reconstruction filters (24 taps)
__constant__ float REC_LO_C[24] = {
    0.0008923136685823146f, -0.0016294920126017326f, -0.0073461663276420935f,
    0.016068943964776348f, 0.026682300156053072f, -0.08126669968087875f,
    -0.05607731331675481f, 0.41530840703043026f, 0.782238930920499f,
    0.4343860564914685f, -0.06662747426342504f, -0.09622044203398798f,
    0.03933442712333749f, 0.025082261844864097f, -0.015211731527946259f,
    -0.00565828668661072f, 0.003751436157278457f, 0.0012665619292989445f,
    -0.0005890207562443383f, -0.00025997455248771324f, 6.233903446100713e-05f,
    3.1229875865345646e-05f, -3.2596802368833675e-06f, -1.7849850030882614e-06f
};
__constant__ float REC_HI_C[24] = {
    -1.7849850030882614e-06f, 3.2596802368833675e-06f, 3.1229875865345646e-05f,
    -6.233903446100713e-05f, -0.00025997455248771324f, 0.0005890207562443383f,
    0.0012665619292989445f, -0.003751436157278457f, -0.00565828668661072f,
    0.015211731527946259f, 0.025082261844864097f, -0.03933442712333749f,
    -0.09622044203398798f, 0.06662747426342504f, 0.4343860564914685f,
    -0.782238930920499f, 0.41530840703043026f, 0.05607731331675481f,
    -0.08126669968087875f, -0.026682300156053072f, 0.016068943964776348f,
    0.0073461663276420935f, -0.0016294920126017326f, -0.0008923136685823146f
};

// Scratch (static device globals; per-plane strides sized for the largest plane)
#define S_LO1 262144    // C*128*64
#define S_MID 524288    // C*128*128
#define S_LO2 1048576   // C*256*128
__device__ float g_lo1[6 * S_LO1];
__device__ float g_hi1[6 * S_LO1];
__device__ float g_mid[6 * S_MID];
__device__ float g_lo2[6 * S_LO2];
__device__ float g_hi2[6 * S_LO2];
// x-paired fp16 planes: [pixel][c] = half2(v[y,x,c], v[y,min(x+1,W-1),c])
__device__ __half2 g_planes2[245760 * CCH];

struct CoefPtrs {
    const float* yl[6];
    const float* yha[6];
    const float* yhb[6];
};

// Stage 1 (paired-parity): level-1 H-axis synthesis.
// in: yl[C,64,w4], yhb[C,3,64,w4] -> lo1,hi1 [C,128,w4]
// One thread -> output rows i=2s, 2s+1 (share all 4 loads per tap).
__global__ void k_stage1(CoefPtrs P) {
    const int pl = blockIdx.y;
    const int w4 = c_W[pl] >> 2;
    const int n = CCH * 64 * w4;             // pairs
    const int tid = blockIdx.x * blockDim.x + threadIdx.x;
    if (tid >= n) return;
    const int x = tid % w4;
    const int s = (tid / w4) & 63;
    const int c = tid / (w4 * 64);
    const float* yl = P.yl[pl];
    const float* yhb = P.yhb[pl];
    const int bandStride = 64 * w4;
    float lo0 = 0.f, lo1v = 0.f, hi0 = 0.f, hi1v = 0.f;
#pragma unroll
    for (int m = 0; m < 12; m++) {
        int row = s - m; if (row < 0) row += 64;
        const float a  = yl [(c * 64 + row) * w4 + x];
        const int b0i  = ((c * 3 + 0) * 64 + row) * w4 + x;
        const float b0 = yhb[b0i];
        const float b1 = yhb[b0i + bandStride];
        const float b2 = yhb[b0i + 2 * bandStride];
        const float fl0 = REC_LO_C[2 * m],     fh0 = REC_HI_C[2 * m];
        const float fl1 = REC_LO_C[2 * m + 1], fh1 = REC_HI_C[2 * m + 1];
        lo0  += fl0 * a  + fh0 * b0;
        lo1v += fl1 * a  + fh1 * b0;
        hi0  += fl0 * b1 + fh0 * b2;
        hi1v += fl1 * b1 + fh1 * b2;
    }
    const int ob = pl * S_LO1 + (c * 128 + 2 * s) * w4 + x;
    g_lo1[ob]      = lo0;
    g_lo1[ob + w4] = lo1v;
    g_hi1[ob]      = hi0;
    g_hi1[ob + w4] = hi1v;
}

// Stage 2 (paired parity): level-1 W-axis synthesis.
// in: lo1,hi1 [C,128,w4] -> mid [C,128,w2]. One thread -> outputs j=2s,2s+1.
__global__ void k_stage2() {
    const int pl = blockIdx.y;
    const int w2 = c_W[pl] >> 1;
    const int w4 = w2 >> 1;
    const int n = CCH * 128 * w4;            // pairs
    const int tid = blockIdx.x * blockDim.x + threadIdx.x;
    if (tid >= n) return;
    const int s = tid % w4;
    const int i = (tid / w4) & 127;
    const int c = tid / (w4 * 128);
    const int base = pl * S_LO1 + (c * 128 + i) * w4;
    float v0 = 0.f, v1 = 0.f;
#pragma unroll
    for (int m = 0; m < 12; m++) {
        int col = s - m; if (col < 0) col += w4;
        const float lv = g_lo1[base + col];
        const float hv = g_hi1[base + col];
        v0 += REC_LO_C[2 * m]     * lv + REC_HI_C[2 * m]     * hv;
        v1 += REC_LO_C[2 * m + 1] * lv + REC_HI_C[2 * m + 1] * hv;
    }
    const int ob = pl * S_MID + (c * 128 + i) * w2 + 2 * s;
    g_mid[ob]     = v0;
    g_mid[ob + 1] = v1;
}

// Stage 3 (paired-parity): level-2 H-axis synthesis.
// in: mid [C,128,w2], yha [C,3,128,w2] -> lo2,hi2 [C,256,w2]
// One thread -> output rows i=2s, 2s+1 (share all 4 loads per tap).
__global__ void k_stage3(CoefPtrs P) {
    const int pl = blockIdx.y;
    const int w2 = c_W[pl] >> 1;
    const int n = CCH * 128 * w2;            // pairs
    const int tid = blockIdx.x * blockDim.x + threadIdx.x;
    if (tid >= n) return;
    const int x = tid % w2;
    const int s = (tid / w2) & 127;
    const int c = tid / (w2 * 128);
    const float* yha = P.yha[pl];
    const int bandStride = 128 * w2;
    const float* midP = g_mid + pl * S_MID;
    float lo0 = 0.f, lo1v = 0.f, hi0 = 0.f, hi1v = 0.f;
#pragma unroll
    for (int m = 0; m < 12; m++) {
        int row = s - m; if (row < 0) row += 128;
        const float mv = midP[(c * 128 + row) * w2 + x];
        const int a0i  = ((c * 3 + 0) * 128 + row) * w2 + x;
        const float a0 = yha[a0i];
        const float a1 = yha[a0i + bandStride];
        const float a2 = yha[a0i + 2 * bandStride];
        const float fl0 = REC_LO_C[2 * m],     fh0 = REC_HI_C[2 * m];
        const float fl1 = REC_LO_C[2 * m + 1], fh1 = REC_HI_C[2 * m + 1];
        lo0  += fl0 * mv + fh0 * a0;
        lo1v += fl1 * mv + fh1 * a0;
        hi0  += fl0 * a1 + fh0 * a2;
        hi1v += fl1 * a1 + fh1 * a2;
    }
    const int ob = pl * S_LO2 + (c * 256 + 2 * s) * w2 + x;
    g_lo2[ob]      = lo0;
    g_lo2[ob + w2] = lo1v;
    g_hi2[ob]      = hi0;
    g_hi2[ob + w2] = hi1v;
}

// Stage 4 (row-tiled, paired-parity, wrap-padded smem, x-paired output):
// level-2 W-axis synthesis + transpose to x-paired half2 layout.
// Smem rows are padded with the 11 wrap-around columns so taps use
// compile-time immediate offsets (no per-tap wrap predicate / index add).
// Stride 141 (=13 mod 32, gcd 1) keeps lane=c reads conflict-free.
__global__ void __launch_bounds__(256) k_stage4() {
    const int pl = blockIdx.y;
    const int W = c_W[pl];
    const int w2 = W >> 1;
    const int y = blockIdx.x;

    __shared__ float lo_s[32][141];    // [c][11 wrap pads | w2 cols]
    __shared__ float hi_s[32][141];
    __shared__ float out_s[256][33];   // [x][c]

    const int sh = (w2 == 128) ? 7 : 5;          // log2(w2)
    const int rowBase = pl * S_LO2 + y * w2;     // + c*256*w2 per channel
    for (int t = threadIdx.x; t < 32 * w2; t += 256) {
        const int c = t >> sh;
        const int col = t & (w2 - 1);
        const int gi = rowBase + c * (256 * w2) + col;
        lo_s[c][11 + col] = g_lo2[gi];
        hi_s[c][11 + col] = g_hi2[gi];
    }
    // wrap pads: k=0..10 holds logical col w2-11+k
    for (int t = threadIdx.x; t < 32 * 11; t += 256) {
        const int c = t / 11;
        const int k = t % 11;
        const int gi = rowBase + c * (256 * w2) + (w2 - 11 + k);
        lo_s[c][k] = g_lo2[gi];
        hi_s[c][k] = g_hi2[gi];
    }
    __syncthreads();

    const int nPairs = w2 * CCH;                  // one thread -> 2 outputs
    for (int t = threadIdx.x; t < nPairs; t += 256) {
        const int c = t & 31;
        const int s = t >> 5;
        const float* lp = &lo_s[c][11 + s];       // taps at lp[-m]
        const float* hp = &hi_s[c][11 + s];
        float v0 = 0.f, v1 = 0.f;                 // parity 0 / parity 1
#pragma unroll
        for (int m = 0; m < 12; m++) {
            const float lv = lp[-m];
            const float hv = hp[-m];
            v0 += REC_LO_C[2 * m]     * lv + REC_HI_C[2 * m]     * hv;
            v1 += REC_LO_C[2 * m + 1] * lv + REC_HI_C[2 * m + 1] * hv;
        }
        out_s[2 * s][c]     = v0;
        out_s[2 * s + 1][c] = v1;
    }
    __syncthreads();

    __half2* __restrict__ outRow = g_planes2 + ((size_t)(c_POFF[pl] + y * W)) * CCH;
    const int n = W * CCH;
    for (int t = threadIdx.x; t < n; t += 256) {
        const int c = t & 31;
        const int x = t >> 5;
        const int x1 = (x + 1 < W) ? x + 1 : W - 1;
        outRow[x * CCH + c] = __floats2half2_rn(out_s[x][c], out_s[x1][c]);
    }
}

// Phase 2: warp per point, lane = channel. Lanes 0-5 compute the 6 planes'
// coords IN PARALLEL; shfl broadcasts (base, wx, wy); 12 half2 loads +
// fp32 interp + product.
__global__ void __launch_bounds__(256) k_sample(const float* __restrict__ pts,
                                                const float* __restrict__ ts,
                                                float* __restrict__ out,
                                                int nPts) {
    const int warp = (blockIdx.x * blockDim.x + threadIdx.x) >> 5;
    const int lane = threadIdx.x & 31;
    if (warp >= nPts) return;

    const float inv = -1.0f / 1.3f;   // pts_n = -pts/B
    const float p0 = pts[warp * 3 + 0] * inv;
    const float p1 = pts[warp * 3 + 1] * inv;
    const float p2 = pts[warp * 3 + 2] * inv;
    const float p3 = ts[warp] * 2.0f - 1.0f;

    // Per-lane plane coords (lanes 0-5 meaningful):
    // QIDX = {0,0,3,1,3,3} -> cx; RIDX = {1,2,0,2,1,2} -> cy
    const float cx = (lane < 2) ? p0 : ((lane == 3) ? p1 : p3);
    const float cy = (lane == 0 || lane == 4) ? p1
                   : ((lane == 2) ? p0 : p2);
    // W per plane {256,256,64,256,64,64}
    const bool small = (lane == 2 || lane >= 4);
    const float Wm1 = small ? 63.0f : 255.0f;
    const int   Wi  = small ? 64 : 256;
    const int   poff = c_POFF[(lane < 6) ? lane : 0];

    float xf = fminf(fmaxf((cx + 1.0f) * 0.5f * Wm1, 0.0f), Wm1);
    float yf = fminf(fmaxf((cy + 1.0f) * 0.5f * 255.0f, 0.0f), 255.0f);
    float x0f = fminf(floorf(xf), Wm1 - 1.0f);   // xf >= 0 already
    float y0f = fminf(floorf(yf), 254.0f);
    const float wx = xf - x0f;
    const float wy = yf - y0f;
    const int  base = (poff + (int)y0f * Wi + (int)x0f) * CCH;

    constexpr int PW[6] = {256, 256, 64, 256, 64, 64};

    float prod = 1.0f;
#pragma unroll
    for (int ii = 0; ii < 6; ii++) {
        const int   b  = __shfl_sync(0xffffffffu, base, ii);
        const float wxb = __shfl_sync(0xffffffffu, wx, ii);
        const float wyb = __shfl_sync(0xffffffffu, wy, ii);
        const int i00 = b + lane;
        const __half2 a2 = g_planes2[i00];                   // (v00, v01)
        const __half2 b2 = g_planes2[i00 + PW[ii] * CCH];    // (v10, v11)
        const float2 fa = __half22float2(a2);
        const float2 fb = __half22float2(b2);
        const float r0 = fa.x + wxb * (fa.y - fa.x);
        const float r1 = fb.x + wxb * (fb.y - fb.x);
        prod *= r0 + wyb * (r1 - r0);
    }
    out[(size_t)warp * CCH + lane] = prod;
}

extern "C" void kernel_launch(void* const* d_in, const int* in_sizes, int n_in,
                              void* d_out, int out_size) {
    const float* pts = (const float*)d_in[0];
    const float* ts  = (const float*)d_in[1];
    CoefPtrs P;
    for (int i = 0; i < 6; i++) {
        P.yl[i]  = (const float*)d_in[2 + 3 * i];
        P.yha[i] = (const float*)d_in[3 + 3 * i];
        P.yhb[i] = (const float*)d_in[4 + 3 * i];
    }
    float* out = (float*)d_out;
    const int nPts = in_sizes[1];   // timestamps count = N

    dim3 blk(256);
    k_stage1<<<dim3((CCH * 64 * 64 + 255) / 256, 6), blk>>>(P);    // pairs, w4 max 64
    k_stage2<<<dim3((CCH * 128 * 64 + 255) / 256, 6), blk>>>();    // pairs, w4 max 64
    k_stage3<<<dim3((CCH * 128 * 128 + 255) / 256, 6), blk>>>(P);  // pairs, w2 max 128
    k_stage4<<<dim3(256, 6), blk>>>();

    const int totalThreads = nPts * 32;
    k_sample<<<(totalThreads + 255) / 256, 256>>>(pts, ts, out, nPts);
}